// round 12
// baseline (speedup 1.0000x reference)
#include <cuda_runtime.h>
#include <math.h>
#include <stdint.h>

// output [B=2, C=8, H=128, W=128, D=128] fp32.
// t = where(x > 0.5, x, 0); per-(b,c): s = sum t, sy = sum t*(h/H), sx, sz analog.
// centroids = s?/s; loss = sum over 8 relations of mean_b((diff - gt)^2), nan/inf->0.
//
// .cv path experiment: identical structure to best (25.1us) kernel, but loads
// are ld.global.cv.v4.b64 (volatile read-through) instead of .nc + evict hints
// (hints proven no-op: RESIDENT_CH=8 vs 12 -> identical timing).
// Grid 592 = 4*148 (one balanced wave), 37 blocks/channel, channel-pure.

#define NCH          16
#define UNITS_PER_CH 512
#define BLK_PER_CH   37
#define NBLOCKS      (NCH * BLK_PER_CH)   // 592
#define THREADS      256

__device__ float g_partials[NBLOCKS * 4];   // per block: {s, sy, sx, sz}
__device__ int   g_count = 0;

__constant__ int   c_rel_i[8] = {0, 1, 2, 3, 4, 5, 6, 0};
__constant__ int   c_rel_j[8] = {1, 2, 3, 4, 5, 6, 7, 7};
__constant__ float c_gt_y[8]  = { 0.1f,  0.0f, -0.1f,  0.0f,  0.05f,  0.0f, 0.1f, -0.05f};
__constant__ float c_gt_x[8]  = { 0.0f,  0.1f,  0.05f, 0.0f, -0.05f,  0.1f, 0.0f,  0.05f};
__constant__ float c_gt_z[8]  = { 0.05f, 0.0f,  0.0f,  0.1f,  0.0f, -0.1f, 0.0f,  0.05f};

__device__ __forceinline__ float nan0(float x) { return isfinite(x) ? x : 0.f; }

struct F8 { uint64_t r0, r1, r2, r3; };

__device__ __forceinline__ F8 ldg256_cv(const float* p) {
    F8 o;
    asm volatile("ld.global.cv.v4.b64 {%0,%1,%2,%3}, [%4];"
        : "=l"(o.r0), "=l"(o.r1), "=l"(o.r2), "=l"(o.r3) : "l"(p));
    return o;
}

__device__ __forceinline__ float lo32(uint64_t r) { return __uint_as_float((uint32_t)r); }
__device__ __forceinline__ float hi32(uint64_t r) { return __uint_as_float((uint32_t)(r >> 32)); }

__global__ void __launch_bounds__(THREADS)
gsl_fused_kernel(const float* __restrict__ in, float* __restrict__ out, int out_size) {
    const int tid = threadIdx.x;
    const float inv = 1.0f / 128.0f;

    const int ch = blockIdx.x / BLK_PER_CH;
    const int g  = blockIdx.x - ch * BLK_PER_CH;        // 0..36
    const int nu = (UNITS_PER_CH - g + BLK_PER_CH - 1) / BLK_PER_CH;  // 13 or 14

    const float* chbase = in + (size_t)ch * (UNITS_PER_CH * 4096);

    // element idx = u*4096 + j*8 + e, j = phase*256 + tid
    // z = (tid & 15)*8 + e  (thread-constant weights wz[0..7])
    // w = (u&3)*32 + phase*16 + (tid>>4)
    // h = u >> 2
    const float z0 = (float)((tid & 15) << 3) * inv;
    float wz[8];
    #pragma unroll
    for (int e = 0; e < 8; ++e) wz[e] = z0 + (float)e * inv;
    const float cx_t = (float)(tid >> 4) * inv;

    float s = 0.f, sy = 0.f, sx = 0.f, sz = 0.f;

    int u = g;
    const float* p0 = chbase + (size_t)u * 4096 + tid * 8;
    F8 a0 = ldg256_cv(p0);
    F8 a1 = ldg256_cv(p0 + 2048);

    for (int k = 0; k < nu; ++k) {
        const int u_next = u + BLK_PER_CH;
        F8 n0, n1;
        if (k + 1 < nu) {
            const float* q = chbase + (size_t)u_next * 4096 + tid * 8;
            n0 = ldg256_cv(q);
            n1 = ldg256_cv(q + 2048);
        }

        const float cy  = (float)(u >> 2) * inv;
        const float cxb = (float)((u & 3) << 5) * inv + cx_t;

        #pragma unroll
        for (int ph = 0; ph < 2; ++ph) {
            F8 v = (ph == 0) ? a0 : a1;
            const float cx = cxb + (float)(ph * 16) * inv;

            float f0 = lo32(v.r0), f1 = hi32(v.r0);
            float f2 = lo32(v.r1), f3 = hi32(v.r1);
            float f4 = lo32(v.r2), f5 = hi32(v.r2);
            float f6 = lo32(v.r3), f7 = hi32(v.r3);

            float t0 = f0 > 0.5f ? f0 : 0.f;
            float t1 = f1 > 0.5f ? f1 : 0.f;
            float t2 = f2 > 0.5f ? f2 : 0.f;
            float t3 = f3 > 0.5f ? f3 : 0.f;
            float t4 = f4 > 0.5f ? f4 : 0.f;
            float t5 = f5 > 0.5f ? f5 : 0.f;
            float t6 = f6 > 0.5f ? f6 : 0.f;
            float t7 = f7 > 0.5f ? f7 : 0.f;

            float ts = ((t0 + t1) + (t2 + t3)) + ((t4 + t5) + (t6 + t7));
            s += ts;
            sy = fmaf(ts, cy, sy);
            sx = fmaf(ts, cx, sx);
            float z01 = fmaf(t0, wz[0], t1 * wz[1]);
            float z23 = fmaf(t2, wz[2], t3 * wz[3]);
            float z45 = fmaf(t4, wz[4], t5 * wz[5]);
            float z67 = fmaf(t6, wz[6], t7 * wz[7]);
            sz += (z01 + z23) + (z45 + z67);
        }

        u = u_next;
        a0 = n0; a1 = n1;
    }

    // block reduce (s, sy, sx, sz)
    #pragma unroll
    for (int off = 16; off > 0; off >>= 1) {
        s  += __shfl_down_sync(0xFFFFFFFFu, s,  off);
        sy += __shfl_down_sync(0xFFFFFFFFu, sy, off);
        sx += __shfl_down_sync(0xFFFFFFFFu, sx, off);
        sz += __shfl_down_sync(0xFFFFFFFFu, sz, off);
    }

    __shared__ float sh[THREADS / 32][4];
    const int lane = tid & 31;
    const int wid  = tid >> 5;
    if (lane == 0) { sh[wid][0] = s; sh[wid][1] = sy; sh[wid][2] = sx; sh[wid][3] = sz; }
    __syncthreads();

    __shared__ bool is_last;
    if (wid == 0) {
        float a = (lane < THREADS / 32) ? sh[lane][0] : 0.f;
        float b = (lane < THREADS / 32) ? sh[lane][1] : 0.f;
        float c = (lane < THREADS / 32) ? sh[lane][2] : 0.f;
        float d = (lane < THREADS / 32) ? sh[lane][3] : 0.f;
        #pragma unroll
        for (int off = 4; off > 0; off >>= 1) {
            a += __shfl_down_sync(0xFFFFFFFFu, a, off);
            b += __shfl_down_sync(0xFFFFFFFFu, b, off);
            c += __shfl_down_sync(0xFFFFFFFFu, c, off);
            d += __shfl_down_sync(0xFFFFFFFFu, d, off);
        }
        if (lane == 0) {
            float4 pp; pp.x = a; pp.y = b; pp.z = c; pp.w = d;
            reinterpret_cast<float4*>(g_partials)[blockIdx.x] = pp;
            __threadfence();
            int prev = atomicAdd(&g_count, 1);
            is_last = (prev == NBLOCKS - 1);
        }
    }
    __syncthreads();

    if (!is_last) return;

    // ---- final reduction: this block only ----
    __shared__ float cen_y[NCH], cen_x[NCH], cen_z[NCH];

    for (int c = wid; c < NCH; c += THREADS / 32) {
        const int base = c * BLK_PER_CH;
        volatile const float* p0v = &g_partials[(base + lane) * 4];
        float a = p0v[0], b = p0v[1], cc = p0v[2], d = p0v[3];
        if (lane < BLK_PER_CH - 32) {
            volatile const float* p1v = &g_partials[(base + 32 + lane) * 4];
            a += p1v[0]; b += p1v[1]; cc += p1v[2]; d += p1v[3];
        }
        #pragma unroll
        for (int off = 16; off > 0; off >>= 1) {
            a  += __shfl_down_sync(0xFFFFFFFFu, a,  off);
            b  += __shfl_down_sync(0xFFFFFFFFu, b,  off);
            cc += __shfl_down_sync(0xFFFFFFFFu, cc, off);
            d  += __shfl_down_sync(0xFFFFFFFFu, d,  off);
        }
        if (lane == 0) {
            cen_y[c] = b / a;
            cen_x[c] = cc / a;
            cen_z[c] = d / a;
        }
    }
    __syncthreads();

    if (tid == 0) {
        float loss = 0.f;
        #pragma unroll
        for (int r = 0; r < 8; r++) {
            int ci = c_rel_i[r], cj = c_rel_j[r];
            float my = 0.f, mx = 0.f, mz = 0.f;
            #pragma unroll
            for (int b = 0; b < 2; b++) {
                int ii = b * 8 + ci, jj = b * 8 + cj;
                float dy = nan0(cen_y[ii] - cen_y[jj] - c_gt_y[r]);
                float dx = nan0(cen_x[ii] - cen_x[jj] - c_gt_x[r]);
                float dz = nan0(cen_z[ii] - cen_z[jj] - c_gt_z[r]);
                my += dy * dy; mx += dx * dx; mz += dz * dz;
            }
            loss += 0.5f * (my + mx + mz);   // mean over B=2
        }
        out[0] = loss;
        g_count = 0;                          // reset for next graph replay
    }
    for (int i = 1 + tid; i < out_size; i += THREADS) out[i] = 0.f;
}

extern "C" void kernel_launch(void* const* d_in, const int* in_sizes, int n_in,
                              void* d_out, int out_size) {
    const float* in = (const float*)d_in[0];
    gsl_fused_kernel<<<NBLOCKS, THREADS>>>(in, (float*)d_out, out_size);
}

// round 13
// speedup vs baseline: 1.1286x; 1.1286x over previous
#include <cuda_runtime.h>
#include <math.h>
#include <stdint.h>

// output [B=2, C=8, H=128, W=128, D=128] fp32.
// t = where(x > 0.5, x, 0); per-(b,c): s = sum t, sy = sum t*(h/H), sx, sz analog.
// centroids = s?/s; loss = sum over 8 relations of mean_b((diff - gt)^2), nan/inf->0.
//
// Best-known load path (25.1us): .nc + L2 evict hints on 256-bit v4.b64 loads,
// grid 592 = 4*148 one balanced wave, 37 blocks/channel, channel-pure.
// NEW: hierarchical finalize — the last block of each channel reduces that
// channel's 37 partials (overlapping other channels' streaming); the 16th
// channel-finalizer computes the scalar loss. Serial tail ~0.2us.

#define NCH          16
#define RESIDENT_CH  12
#define UNITS_PER_CH 512
#define BLK_PER_CH   37
#define NBLOCKS      (NCH * BLK_PER_CH)   // 592
#define THREADS      256

__device__ float g_partials[NBLOCKS * 4];   // per block: {s, sy, sx, sz}
__device__ float g_cen[NCH * 3];            // per channel: {cy, cx, cz}
__device__ int   g_ch_count[NCH];
__device__ int   g_done = 0;

__constant__ int   c_rel_i[8] = {0, 1, 2, 3, 4, 5, 6, 0};
__constant__ int   c_rel_j[8] = {1, 2, 3, 4, 5, 6, 7, 7};
__constant__ float c_gt_y[8]  = { 0.1f,  0.0f, -0.1f,  0.0f,  0.05f,  0.0f, 0.1f, -0.05f};
__constant__ float c_gt_x[8]  = { 0.0f,  0.1f,  0.05f, 0.0f, -0.05f,  0.1f, 0.0f,  0.05f};
__constant__ float c_gt_z[8]  = { 0.05f, 0.0f,  0.0f,  0.1f,  0.0f, -0.1f, 0.0f,  0.05f};

__device__ __forceinline__ float nan0(float x) { return isfinite(x) ? x : 0.f; }

struct F8 { uint64_t r0, r1, r2, r3; };

__device__ __forceinline__ F8 ldg256_last(const float* p) {
    F8 o;
    asm("ld.global.nc.L2::evict_last.v4.b64 {%0,%1,%2,%3}, [%4];"
        : "=l"(o.r0), "=l"(o.r1), "=l"(o.r2), "=l"(o.r3) : "l"(p));
    return o;
}

__device__ __forceinline__ F8 ldg256_first(const float* p) {
    F8 o;
    asm("ld.global.nc.L2::evict_first.v4.b64 {%0,%1,%2,%3}, [%4];"
        : "=l"(o.r0), "=l"(o.r1), "=l"(o.r2), "=l"(o.r3) : "l"(p));
    return o;
}

__device__ __forceinline__ float lo32(uint64_t r) { return __uint_as_float((uint32_t)r); }
__device__ __forceinline__ float hi32(uint64_t r) { return __uint_as_float((uint32_t)(r >> 32)); }

template <bool RES>
__device__ __forceinline__ void accumulate(const float* __restrict__ chbase,
                                           int g, int nu, int tid,
                                           float& s, float& sy, float& sx, float& sz) {
    const float inv = 1.0f / 128.0f;
    const float z0 = (float)((tid & 15) << 3) * inv;
    float wz[8];
    #pragma unroll
    for (int e = 0; e < 8; ++e) wz[e] = z0 + (float)e * inv;
    const float cx_t = (float)(tid >> 4) * inv;

    int u = g;
    const float* p0 = chbase + (size_t)u * 4096 + tid * 8;
    F8 a0 = RES ? ldg256_last(p0)        : ldg256_first(p0);
    F8 a1 = RES ? ldg256_last(p0 + 2048) : ldg256_first(p0 + 2048);

    for (int k = 0; k < nu; ++k) {
        const int u_next = u + BLK_PER_CH;
        F8 n0, n1;
        if (k + 1 < nu) {
            const float* q = chbase + (size_t)u_next * 4096 + tid * 8;
            n0 = RES ? ldg256_last(q)        : ldg256_first(q);
            n1 = RES ? ldg256_last(q + 2048) : ldg256_first(q + 2048);
        }

        const float cy  = (float)(u >> 2) * inv;
        const float cxb = (float)((u & 3) << 5) * inv + cx_t;

        #pragma unroll
        for (int ph = 0; ph < 2; ++ph) {
            F8 v = (ph == 0) ? a0 : a1;
            const float cx = cxb + (float)(ph * 16) * inv;

            float f0 = lo32(v.r0), f1 = hi32(v.r0);
            float f2 = lo32(v.r1), f3 = hi32(v.r1);
            float f4 = lo32(v.r2), f5 = hi32(v.r2);
            float f6 = lo32(v.r3), f7 = hi32(v.r3);

            float t0 = f0 > 0.5f ? f0 : 0.f;
            float t1 = f1 > 0.5f ? f1 : 0.f;
            float t2 = f2 > 0.5f ? f2 : 0.f;
            float t3 = f3 > 0.5f ? f3 : 0.f;
            float t4 = f4 > 0.5f ? f4 : 0.f;
            float t5 = f5 > 0.5f ? f5 : 0.f;
            float t6 = f6 > 0.5f ? f6 : 0.f;
            float t7 = f7 > 0.5f ? f7 : 0.f;

            float ts = ((t0 + t1) + (t2 + t3)) + ((t4 + t5) + (t6 + t7));
            s += ts;
            sy = fmaf(ts, cy, sy);
            sx = fmaf(ts, cx, sx);
            float z01 = fmaf(t0, wz[0], t1 * wz[1]);
            float z23 = fmaf(t2, wz[2], t3 * wz[3]);
            float z45 = fmaf(t4, wz[4], t5 * wz[5]);
            float z67 = fmaf(t6, wz[6], t7 * wz[7]);
            sz += (z01 + z23) + (z45 + z67);
        }

        u = u_next;
        a0 = n0; a1 = n1;
    }
}

__global__ void __launch_bounds__(THREADS)
gsl_fused_kernel(const float* __restrict__ in, float* __restrict__ out, int out_size) {
    const int tid = threadIdx.x;

    const int ch = blockIdx.x / BLK_PER_CH;
    const int g  = blockIdx.x - ch * BLK_PER_CH;        // 0..36
    const int nu = (UNITS_PER_CH - g + BLK_PER_CH - 1) / BLK_PER_CH;  // 13 or 14

    const float* chbase = in + (size_t)ch * (UNITS_PER_CH * 4096);

    float s = 0.f, sy = 0.f, sx = 0.f, sz = 0.f;

    if (ch < RESIDENT_CH)
        accumulate<true >(chbase, g, nu, tid, s, sy, sx, sz);
    else
        accumulate<false>(chbase, g, nu, tid, s, sy, sx, sz);

    // block reduce (s, sy, sx, sz)
    #pragma unroll
    for (int off = 16; off > 0; off >>= 1) {
        s  += __shfl_down_sync(0xFFFFFFFFu, s,  off);
        sy += __shfl_down_sync(0xFFFFFFFFu, sy, off);
        sx += __shfl_down_sync(0xFFFFFFFFu, sx, off);
        sz += __shfl_down_sync(0xFFFFFFFFu, sz, off);
    }

    __shared__ float sh[THREADS / 32][4];
    const int lane = tid & 31;
    const int wid  = tid >> 5;
    if (lane == 0) { sh[wid][0] = s; sh[wid][1] = sy; sh[wid][2] = sx; sh[wid][3] = sz; }
    __syncthreads();
    if (wid != 0) return;                     // warps 1-7 done

    // warp 0: fold 8 warp-partials, publish, maybe finalize
    float a = (lane < THREADS / 32) ? sh[lane][0] : 0.f;
    float b = (lane < THREADS / 32) ? sh[lane][1] : 0.f;
    float c = (lane < THREADS / 32) ? sh[lane][2] : 0.f;
    float d = (lane < THREADS / 32) ? sh[lane][3] : 0.f;
    #pragma unroll
    for (int off = 4; off > 0; off >>= 1) {
        a += __shfl_down_sync(0xFFFFFFFFu, a, off);
        b += __shfl_down_sync(0xFFFFFFFFu, b, off);
        c += __shfl_down_sync(0xFFFFFFFFu, c, off);
        d += __shfl_down_sync(0xFFFFFFFFu, d, off);
    }

    int ch_prev = 0;
    if (lane == 0) {
        float4 pp; pp.x = a; pp.y = b; pp.z = c; pp.w = d;
        reinterpret_cast<float4*>(g_partials)[blockIdx.x] = pp;
        __threadfence();
        ch_prev = atomicAdd(&g_ch_count[ch], 1);
    }
    const bool ch_last = __shfl_sync(0xFFFFFFFFu, ch_prev, 0) == (BLK_PER_CH - 1);
    if (!ch_last) return;

    // ---- channel finalize (warp 0 of this channel's last block) ----
    {
        const int base = ch * BLK_PER_CH;
        volatile const float* p0 = &g_partials[(base + lane) * 4];
        float fa = p0[0], fb = p0[1], fc = p0[2], fd = p0[3];
        if (lane < BLK_PER_CH - 32) {
            volatile const float* p1 = &g_partials[(base + 32 + lane) * 4];
            fa += p1[0]; fb += p1[1]; fc += p1[2]; fd += p1[3];
        }
        #pragma unroll
        for (int off = 16; off > 0; off >>= 1) {
            fa += __shfl_down_sync(0xFFFFFFFFu, fa, off);
            fb += __shfl_down_sync(0xFFFFFFFFu, fb, off);
            fc += __shfl_down_sync(0xFFFFFFFFu, fc, off);
            fd += __shfl_down_sync(0xFFFFFFFFu, fd, off);
        }
        int done_prev = 0;
        if (lane == 0) {
            g_cen[ch * 3 + 0] = fb / fa;
            g_cen[ch * 3 + 1] = fc / fa;
            g_cen[ch * 3 + 2] = fd / fa;
            g_ch_count[ch] = 0;               // reset for next graph replay
            __threadfence();
            done_prev = atomicAdd(&g_done, 1);
        }
        const bool all_done = __shfl_sync(0xFFFFFFFFu, done_prev, 0) == (NCH - 1);
        if (!all_done) return;
    }

    // ---- global finalize (one warp total) ----
    if (lane == 0) {
        volatile const float* cen = g_cen;
        float loss = 0.f;
        #pragma unroll
        for (int r = 0; r < 8; r++) {
            int ci = c_rel_i[r], cj = c_rel_j[r];
            float my = 0.f, mx = 0.f, mz = 0.f;
            #pragma unroll
            for (int bb = 0; bb < 2; bb++) {
                int ii = (bb * 8 + ci) * 3, jj = (bb * 8 + cj) * 3;
                float dy = nan0(cen[ii + 0] - cen[jj + 0] - c_gt_y[r]);
                float dx = nan0(cen[ii + 1] - cen[jj + 1] - c_gt_x[r]);
                float dz = nan0(cen[ii + 2] - cen[jj + 2] - c_gt_z[r]);
                my += dy * dy; mx += dx * dx; mz += dz * dz;
            }
            loss += 0.5f * (my + mx + mz);   // mean over B=2
        }
        out[0] = loss;
        g_done = 0;                          // reset for next graph replay
    }
    for (int i = 1 + lane; i < out_size; i += 32) out[i] = 0.f;
}

extern "C" void kernel_launch(void* const* d_in, const int* in_sizes, int n_in,
                              void* d_out, int out_size) {
    const float* in = (const float*)d_in[0];
    gsl_fused_kernel<<<NBLOCKS, THREADS>>>(in, (float*)d_out, out_size);
}

// round 15
// speedup vs baseline: 1.2069x; 1.0694x over previous
#include <cuda_runtime.h>
#include <math.h>
#include <stdint.h>

// output [B=2, C=8, H=128, W=128, D=128] fp32.
// t = where(x > 0.5, x, 0); per-(b,c): s = sum t, sy = sum t*(h/H), sx, sz analog.
// centroids = s?/s; loss = sum over 8 relations of mean_b((diff - gt)^2), nan/inf->0.
//
// Load path: .nc + L2 evict hints on 256-bit v4.b64 loads; grid 592 = 4*148
// one balanced wave, 37 blocks/channel, channel-pure; hierarchical finalize.
// 8 KiB work units (1024/channel) -> 27/28 units per block (3.7% imbalance),
// depth-2 unit pipeline. R14 fix: h = u>>3, w = (u&7)*16 + (tid>>4)
// (unit = 2048 floats; h-slice = 16384 floats = 8 units).

#define NCH          16
#define RESIDENT_CH  12
#define UNITS_PER_CH 1024                  // 8 KiB units (2048 floats)
#define BLK_PER_CH   37
#define NBLOCKS      (NCH * BLK_PER_CH)    // 592
#define THREADS      256

__device__ float g_partials[NBLOCKS * 4];  // per block: {s, sy, sx, sz}
__device__ float g_cen[NCH * 3];           // per channel: {cy, cx, cz}
__device__ int   g_ch_count[NCH];
__device__ int   g_done = 0;

__constant__ int   c_rel_i[8] = {0, 1, 2, 3, 4, 5, 6, 0};
__constant__ int   c_rel_j[8] = {1, 2, 3, 4, 5, 6, 7, 7};
__constant__ float c_gt_y[8]  = { 0.1f,  0.0f, -0.1f,  0.0f,  0.05f,  0.0f, 0.1f, -0.05f};
__constant__ float c_gt_x[8]  = { 0.0f,  0.1f,  0.05f, 0.0f, -0.05f,  0.1f, 0.0f,  0.05f};
__constant__ float c_gt_z[8]  = { 0.05f, 0.0f,  0.0f,  0.1f,  0.0f, -0.1f, 0.0f,  0.05f};

__device__ __forceinline__ float nan0(float x) { return isfinite(x) ? x : 0.f; }

struct F8 { uint64_t r0, r1, r2, r3; };

__device__ __forceinline__ F8 ldg256_last(const float* p) {
    F8 o;
    asm("ld.global.nc.L2::evict_last.v4.b64 {%0,%1,%2,%3}, [%4];"
        : "=l"(o.r0), "=l"(o.r1), "=l"(o.r2), "=l"(o.r3) : "l"(p));
    return o;
}

__device__ __forceinline__ F8 ldg256_first(const float* p) {
    F8 o;
    asm("ld.global.nc.L2::evict_first.v4.b64 {%0,%1,%2,%3}, [%4];"
        : "=l"(o.r0), "=l"(o.r1), "=l"(o.r2), "=l"(o.r3) : "l"(p));
    return o;
}

__device__ __forceinline__ float lo32(uint64_t r) { return __uint_as_float((uint32_t)r); }
__device__ __forceinline__ float hi32(uint64_t r) { return __uint_as_float((uint32_t)(r >> 32)); }

template <bool RES>
__device__ __forceinline__ void accumulate(const float* __restrict__ chbase,
                                           int g, int nu, int tid,
                                           float& s, float& sy, float& sx, float& sz) {
    const float inv = 1.0f / 128.0f;

    // element idx = u*2048 + tid*8 + e ; h-slice = 16384 floats = 8 units
    // h = u >> 3
    // w = (u & 7)*16 + (tid >> 4)
    // z = (tid & 15)*8 + e   (thread-constant weights wz[0..7])
    const float z0 = (float)((tid & 15) << 3) * inv;
    float wz[8];
    #pragma unroll
    for (int e = 0; e < 8; ++e) wz[e] = z0 + (float)e * inv;
    const float cx_t = (float)(tid >> 4) * inv;

    const float* base_t = chbase + tid * 8;

    F8 buf0, buf1;
    buf0 = RES ? ldg256_last(base_t + (size_t)g * 2048)
               : ldg256_first(base_t + (size_t)g * 2048);
    if (nu > 1) {
        const float* q = base_t + (size_t)(g + BLK_PER_CH) * 2048;
        buf1 = RES ? ldg256_last(q) : ldg256_first(q);
    }

    int u = g;
    for (int k = 0; k < nu; ++k) {
        F8 v = (k & 1) ? buf1 : buf0;

        // prefetch unit k+2 into the slot just freed
        if (k + 2 < nu) {
            const float* q = base_t + (size_t)(u + 2 * BLK_PER_CH) * 2048;
            F8 n = RES ? ldg256_last(q) : ldg256_first(q);
            if (k & 1) buf1 = n; else buf0 = n;
        }

        const float cy = (float)(u >> 3) * inv;
        const float cx = (float)((u & 7) << 4) * inv + cx_t;

        float f0 = lo32(v.r0), f1 = hi32(v.r0);
        float f2 = lo32(v.r1), f3 = hi32(v.r1);
        float f4 = lo32(v.r2), f5 = hi32(v.r2);
        float f6 = lo32(v.r3), f7 = hi32(v.r3);

        float t0 = f0 > 0.5f ? f0 : 0.f;
        float t1 = f1 > 0.5f ? f1 : 0.f;
        float t2 = f2 > 0.5f ? f2 : 0.f;
        float t3 = f3 > 0.5f ? f3 : 0.f;
        float t4 = f4 > 0.5f ? f4 : 0.f;
        float t5 = f5 > 0.5f ? f5 : 0.f;
        float t6 = f6 > 0.5f ? f6 : 0.f;
        float t7 = f7 > 0.5f ? f7 : 0.f;

        float ts = ((t0 + t1) + (t2 + t3)) + ((t4 + t5) + (t6 + t7));
        s += ts;
        sy = fmaf(ts, cy, sy);
        sx = fmaf(ts, cx, sx);
        float z01 = fmaf(t0, wz[0], t1 * wz[1]);
        float z23 = fmaf(t2, wz[2], t3 * wz[3]);
        float z45 = fmaf(t4, wz[4], t5 * wz[5]);
        float z67 = fmaf(t6, wz[6], t7 * wz[7]);
        sz += (z01 + z23) + (z45 + z67);

        u += BLK_PER_CH;
    }
}

__global__ void __launch_bounds__(THREADS)
gsl_fused_kernel(const float* __restrict__ in, float* __restrict__ out, int out_size) {
    const int tid = threadIdx.x;

    const int ch = blockIdx.x / BLK_PER_CH;
    const int g  = blockIdx.x - ch * BLK_PER_CH;        // 0..36
    const int nu = (UNITS_PER_CH - g + BLK_PER_CH - 1) / BLK_PER_CH;  // 27 or 28

    const float* chbase = in + (size_t)ch * (UNITS_PER_CH * 2048);

    float s = 0.f, sy = 0.f, sx = 0.f, sz = 0.f;

    if (ch < RESIDENT_CH)
        accumulate<true >(chbase, g, nu, tid, s, sy, sx, sz);
    else
        accumulate<false>(chbase, g, nu, tid, s, sy, sx, sz);

    // block reduce (s, sy, sx, sz)
    #pragma unroll
    for (int off = 16; off > 0; off >>= 1) {
        s  += __shfl_down_sync(0xFFFFFFFFu, s,  off);
        sy += __shfl_down_sync(0xFFFFFFFFu, sy, off);
        sx += __shfl_down_sync(0xFFFFFFFFu, sx, off);
        sz += __shfl_down_sync(0xFFFFFFFFu, sz, off);
    }

    __shared__ float sh[THREADS / 32][4];
    const int lane = tid & 31;
    const int wid  = tid >> 5;
    if (lane == 0) { sh[wid][0] = s; sh[wid][1] = sy; sh[wid][2] = sx; sh[wid][3] = sz; }
    __syncthreads();
    if (wid != 0) return;                     // warps 1-7 done

    // warp 0: fold 8 warp-partials, publish, maybe finalize
    float a = (lane < THREADS / 32) ? sh[lane][0] : 0.f;
    float b = (lane < THREADS / 32) ? sh[lane][1] : 0.f;
    float c = (lane < THREADS / 32) ? sh[lane][2] : 0.f;
    float d = (lane < THREADS / 32) ? sh[lane][3] : 0.f;
    #pragma unroll
    for (int off = 4; off > 0; off >>= 1) {
        a += __shfl_down_sync(0xFFFFFFFFu, a, off);
        b += __shfl_down_sync(0xFFFFFFFFu, b, off);
        c += __shfl_down_sync(0xFFFFFFFFu, c, off);
        d += __shfl_down_sync(0xFFFFFFFFu, d, off);
    }

    int ch_prev = 0;
    if (lane == 0) {
        float4 pp; pp.x = a; pp.y = b; pp.z = c; pp.w = d;
        reinterpret_cast<float4*>(g_partials)[blockIdx.x] = pp;
        __threadfence();
        ch_prev = atomicAdd(&g_ch_count[ch], 1);
    }
    const bool ch_last = __shfl_sync(0xFFFFFFFFu, ch_prev, 0) == (BLK_PER_CH - 1);
    if (!ch_last) return;

    // ---- channel finalize (warp 0 of this channel's last block) ----
    {
        const int base = ch * BLK_PER_CH;
        volatile const float* p0 = &g_partials[(base + lane) * 4];
        float fa = p0[0], fb = p0[1], fc = p0[2], fd = p0[3];
        if (lane < BLK_PER_CH - 32) {
            volatile const float* p1 = &g_partials[(base + 32 + lane) * 4];
            fa += p1[0]; fb += p1[1]; fc += p1[2]; fd += p1[3];
        }
        #pragma unroll
        for (int off = 16; off > 0; off >>= 1) {
            fa += __shfl_down_sync(0xFFFFFFFFu, fa, off);
            fb += __shfl_down_sync(0xFFFFFFFFu, fb, off);
            fc += __shfl_down_sync(0xFFFFFFFFu, fc, off);
            fd += __shfl_down_sync(0xFFFFFFFFu, fd, off);
        }
        int done_prev = 0;
        if (lane == 0) {
            g_cen[ch * 3 + 0] = fb / fa;
            g_cen[ch * 3 + 1] = fc / fa;
            g_cen[ch * 3 + 2] = fd / fa;
            g_ch_count[ch] = 0;               // reset for next graph replay
            __threadfence();
            done_prev = atomicAdd(&g_done, 1);
        }
        const bool all_done = __shfl_sync(0xFFFFFFFFu, done_prev, 0) == (NCH - 1);
        if (!all_done) return;
    }

    // ---- global finalize (one warp total) ----
    if (lane == 0) {
        volatile const float* cen = g_cen;
        float loss = 0.f;
        #pragma unroll
        for (int r = 0; r < 8; r++) {
            int ci = c_rel_i[r], cj = c_rel_j[r];
            float my = 0.f, mx = 0.f, mz = 0.f;
            #pragma unroll
            for (int bb = 0; bb < 2; bb++) {
                int ii = (bb * 8 + ci) * 3, jj = (bb * 8 + cj) * 3;
                float dy = nan0(cen[ii + 0] - cen[jj + 0] - c_gt_y[r]);
                float dx = nan0(cen[ii + 1] - cen[jj + 1] - c_gt_x[r]);
                float dz = nan0(cen[ii + 2] - cen[jj + 2] - c_gt_z[r]);
                my += dy * dy; mx += dx * dx; mz += dz * dz;
            }
            loss += 0.5f * (my + mx + mz);   // mean over B=2
        }
        out[0] = loss;
        g_done = 0;                          // reset for next graph replay
    }
    for (int i = 1 + lane; i < out_size; i += 32) out[i] = 0.f;
}

extern "C" void kernel_launch(void* const* d_in, const int* in_sizes, int n_in,
                              void* d_out, int out_size) {
    const float* in = (const float*)d_in[0];
    gsl_fused_kernel<<<NBLOCKS, THREADS>>>(in, (float*)d_out, out_size);
}